// round 16
// baseline (speedup 1.0000x reference)
#include <cuda_runtime.h>
#include <cuda_bf16.h>
#include <cstdint>

// Embedding gather: out[row,:] = embedding[ids[row],:]
// 4096 rows x 4KB, fp32.
//
// R16 = R8..R15 resubmit (9x broker timeouts; experiment still unmeasured).
// Max-occupancy x MLP=2: 2048 CTAs x 256 threads, 2 rows per CTA. Each
// thread front-batches 2 independent float4 gathers (64 req/warp ~= M_max
// 55), 64 resident warps/SM -> ~8MB chip-wide in flight (2.3x R1).
// __stcs stores (evict-first) keep the embedding table L2-resident across
// graph replays.

#define VEC4 256          // float4 per row (1024 floats)
#define ROWS_PER_CTA 2

__global__ __launch_bounds__(256)
void wordembed_gather_kernel(const int* __restrict__ input_ids,
                             const float4* __restrict__ embedding,
                             float4* __restrict__ out) {
    const int base = blockIdx.x * ROWS_PER_CTA;
    const int t = threadIdx.x;     // 0..255 = float4 column

    // Two indices, one 8B load (base is even -> aligned)
    int2 ids = __ldg((const int2*)(input_ids + base));

    // Front-batched independent gathers (MLP=2 per thread)
    float4 v0 = __ldg(&embedding[(size_t)ids.x * VEC4 + t]);
    float4 v1 = __ldg(&embedding[(size_t)ids.y * VEC4 + t]);

    // Streaming stores: evict-first, keep L2 for the embedding table
    __stcs(&out[(size_t)(base + 0) * VEC4 + t], v0);
    __stcs(&out[(size_t)(base + 1) * VEC4 + t], v1);
}

extern "C" void kernel_launch(void* const* d_in, const int* in_sizes, int n_in,
                              void* d_out, int out_size) {
    const int*    input_ids = (const int*)d_in[0];
    const float4* embedding = (const float4*)d_in[1];
    float4*       out       = (float4*)d_out;

    int n_tokens = in_sizes[0];                  // 4096
    int n_ctas = n_tokens / ROWS_PER_CTA;        // 2048

    wordembed_gather_kernel<<<n_ctas, 256>>>(input_ids, embedding, out);
}